// round 13
// baseline (speedup 1.0000x reference)
#include <cuda_runtime.h>
#include <cuda_bf16.h>
#include <cstdint>

// DifferentiableNLMS: B=32, T=2000, F=513, L=32, mu=0.1, eps=1e-8
// R11 core + software-pipelined prologue: minv/ccs for block n+1 are computed
// from (x(n), x(n+1)) BEFORE serial(n), so the 32-deep (S|CC) packed chain,
// the shuffles and the MUFU.RCPs all overlap the serial recursion as ILP
// instead of extending the per-block critical path.
// Two threads per (b,f): thread h owns taps [16h,16h+16) on an x stream
// shifted by 16*(1-h) (zero-pad makes it exact). Two-step lookahead,
// packed f32x2 FMAs, one shfl64 reduce per 2 steps.

#define NB 32
#define NT 2000
#define NF 513
#define NL 32
#define MU 0.1f
#define EPSV 1e-8f

#define NPAIR (NB * NF)        // 16416 sequences
#define NTHREAD (NPAIR * 2)    // 32832 threads = 1026 full warps
#define NSTEP 16
#define NPB 8
#define NDBL 62                // blocks 0..123 in pairs; block 124 peeled

typedef unsigned long long u64;

__device__ __forceinline__ u64 ffma2(u64 a, u64 b, u64 c) {
    u64 d; asm("fma.rn.f32x2 %0, %1, %2, %3;" : "=l"(d) : "l"(a), "l"(b), "l"(c));
    return d;
}
__device__ __forceinline__ u64 fadd2(u64 a, u64 b) {
    u64 d; asm("add.rn.f32x2 %0, %1, %2;" : "=l"(d) : "l"(a), "l"(b));
    return d;
}
__device__ __forceinline__ u64 pack2(float lo, float hi) {
    u64 d; asm("mov.b64 %0, {%1, %2};" : "=l"(d) : "f"(lo), "f"(hi));
    return d;
}
__device__ __forceinline__ void unpack2(u64 v, float& lo, float& hi) {
    asm("mov.b64 {%0, %1}, %2;" : "=f"(lo), "=f"(hi) : "l"(v));
}
__device__ __forceinline__ u64 shfl64(u64 v) {
    return __shfl_xor_sync(0xFFFFFFFFu, v, 1);
}
__device__ __forceinline__ float shflf(float v) {
    return __shfl_xor_sync(0xFFFFFFFFu, v, 1);
}
__device__ __forceinline__ float negf(float x) {
    return __int_as_float(__float_as_int(x) ^ 0x80000000);
}

__device__ __forceinline__ void prefetch_g(float (&x)[NSTEP], float (&y)[NSTEP],
                                           const float* __restrict__ xp,
                                           const float* __restrict__ yp,
                                           int t, int off)
{
#pragma unroll
    for (int u = 0; u < NSTEP; u++) {
        int ti = t + u - off;
        x[u] = (ti >= 0) ? __ldg(xp + (size_t)ti * NF) : 0.f;
        y[u] = __ldg(yp + (size_t)(t + u) * NF);
    }
}
__device__ __forceinline__ void prefetch_u(float (&x)[NSTEP], float (&y)[NSTEP],
                                           const float* __restrict__ xp,
                                           const float* __restrict__ yp,
                                           int t, int off)
{
#pragma unroll
    for (int u = 0; u < NSTEP; u++) {
        x[u] = __ldg(xp + (size_t)(t + u - off) * NF);
        y[u] = __ldg(yp + (size_t)(t + u) * NF);
    }
}

// Prologue for the NEXT block: drops come from xcur (this block's x), adds
// from xnext. pl = last sample of the block before xcur. Updates SC and pl.
// Produces minv[16] (step sizes) and ccs[8] (lag-1 cross-correlations).
__device__ __forceinline__ void prologue(
    float (&minv)[NSTEP], float (&ccs)[NPB],
    const float (&xcur)[NSTEP], const float (&xnext)[NSTEP],
    u64& SC, float& pl)
{
    float s0a[NPB], s1a[NPB], cca[NPB];
    {
        u64 sc = SC;
#pragma unroll
        for (int p = 0; p < NPB; p++) {
            float a  = p ? xcur[2 * p - 1] : pl;   // x'_{t-17}
            float b  = xcur[2 * p];                // x'_{t-16}
            float cq = xcur[2 * p + 1];            // x'_{t-15}
            float xm1 = p ? xnext[2 * p - 1] : xcur[NSTEP - 1];
            float x0 = xnext[2 * p], x1 = xnext[2 * p + 1];
            // lo: S += x0^2 - b^2 ; hi: CC += xm1*x0 - a*b
            sc = ffma2(pack2(x0, xm1), pack2(x0, x0), sc);
            sc = ffma2(pack2(negf(b), negf(a)), pack2(b, b), sc);
            { float slo, shi; unpack2(sc, slo, shi); s0a[p] = slo; }
            // lo: S += x1^2 - cq^2 ; hi: CC += x0*x1 - b*cq
            sc = ffma2(pack2(x1, x0), pack2(x1, x1), sc);
            sc = ffma2(pack2(negf(cq), negf(b)), pack2(cq, cq), sc);
            { float slo, shi; unpack2(sc, slo, shi); s1a[p] = slo; cca[p] = shi; }
        }
        SC = sc;
    }
    pl = xcur[NSTEP - 1];
#pragma unroll
    for (int p = 0; p < NPB; p++) {
        float s0f = s0a[p] + shflf(s0a[p]);
        float s1f = s1a[p] + shflf(s1a[p]);
        minv[2 * p]     = __fdividef(MU, s0f);   // EPS folded into SC seed
        minv[2 * p + 1] = __fdividef(MU, s1f);
    }
#pragma unroll
    for (int p = 0; p < NPB; p++) {
        ccs[p] = cca[p] + shflf(cca[p]);
    }
}

// Serial recursion only (prologue already done for this block).
__device__ __forceinline__ void serial(
    u64 (&W2)[8], u64 (&P)[8], u64 (&Q)[8], float& xlast,
    const float (&xb)[NSTEP], const float (&yb)[NSTEP],
    const float (&minv)[NSTEP], const float (&ccs)[NPB],
    float* __restrict__ ep, int t0, bool writer)
{
    float xm1_0 = xlast;
#pragma unroll
    for (int p = 0; p < NPB; p++) {
        float xm1 = p ? xb[2 * p - 1] : xm1_0;
        float x0 = xb[2 * p], x1 = xb[2 * p + 1];
        P[p] = pack2(xm1, x0);
        Q[p] = pack2(x0, x1);

        u64 a0 = 0, a1 = 0, b0 = 0, b1 = 0;
#pragma unroll
        for (int i = 0; i < 8; i += 2) {
            a0 = ffma2(W2[i],     P[(p + 1 + i) & 7], a0);
            a1 = ffma2(W2[i + 1], P[(p + 2 + i) & 7], a1);
            b0 = ffma2(W2[i],     Q[(p + 1 + i) & 7], b0);
            b1 = ffma2(W2[i + 1], Q[(p + 2 + i) & 7], b1);
        }
        u64 ap = fadd2(a0, a1);
        u64 aq = fadd2(b0, b1);
        float plo, phi, qlo, qhi;
        unpack2(ap, plo, phi);
        unpack2(aq, qlo, qhi);
        u64 pq = pack2(plo + phi, qlo + qhi);
        u64 pqs = fadd2(pq, shfl64(pq));
        float pt, qt;
        unpack2(pqs, pt, qt);

        float e0 = yb[2 * p] - pt;
        float c0 = e0 * minv[2 * p];
        float e1 = fmaf(-c0, ccs[p], yb[2 * p + 1] - qt);
        float c1 = e1 * minv[2 * p + 1];

        if (writer) {
            ep[(size_t)(t0 + 2 * p) * NF] = e0;
            ep[(size_t)(t0 + 2 * p + 1) * NF] = e1;
        }

        u64 c0p = pack2(c0, c0);
        u64 c1p = pack2(c1, c1);
#pragma unroll
        for (int i = 0; i < 8; i++) {
            W2[i] = ffma2(c1p, Q[(p + 1 + i) & 7],
                          ffma2(c0p, P[(p + 1 + i) & 7], W2[i]));
        }
    }
    xlast = xb[NSTEP - 1];
}

__global__ void __launch_bounds__(128, 2)
nlms_kernel(const float* __restrict__ X, const float* __restrict__ Y,
            const float* __restrict__ Wp, float* __restrict__ out,
            int write_w)
{
    int gtid = blockIdx.x * blockDim.x + threadIdx.x;
    bool valid = (gtid < NTHREAD);
    int g = valid ? gtid : (NTHREAD - 1);   // clamp: no divergent exit
    int h = g & 1;
    int seq = g >> 1;
    int b = seq / NF;
    int f = seq - b * NF;
    int off = 16 * (1 - h);

    size_t base = (size_t)b * NT * NF + f;
    const float* xp = X + base;
    const float* yp = Y + base;
    float* ep = out + base;
    bool writer = (h == 1) && valid;

    u64 W2[8], P[8], Q[8];
#pragma unroll
    for (int i = 0; i < 8; i++) {
        int j = 16 * h + 2 * i;
        float w0 = Wp[((size_t)b * NL + j) * NF + f];
        float w1 = Wp[((size_t)b * NL + j + 1) * NF + f];
        W2[i] = pack2(w0, w1);
        P[i] = 0;
        Q[i] = 0;
    }
    // lo(SC) = norm partial (lane 1 seeds EPS: pair-sum carries exactly one
    // EPS); hi(SC) = lag-1 cross-correlation partial.
    u64 SC = pack2(h ? EPSV : 0.f, 0.f);
    float xlast = 0.f;   // serial carry: previous block's last own-stream x
    float pl = 0.f;      // prologue carry: x two blocks back, last sample

    float xA[NSTEP], yA[NSTEP], xB[NSTEP], yB[NSTEP];
    float minvA[NSTEP], ccsA[NPB], minvB[NSTEP], ccsB[NPB];

    prefetch_g(xA, yA, xp, yp, 0, off);

    // Block-0 prologue against the zero pad (drops are all zero).
    {
        float z[NSTEP];
#pragma unroll
        for (int i = 0; i < NSTEP; i++) z[i] = 0.f;
        prologue(minvA, ccsA, z, xA, SC, pl);
    }

    int t0 = 0;
#pragma unroll 1
    for (int dd = 0; dd < NDBL; dd++) {
        // even half: serial block n, prologue block n+1
        prefetch_u(xB, yB, xp, yp, t0 + NSTEP, off);
        prologue(minvB, ccsB, xA, xB, SC, pl);
        serial(W2, P, Q, xlast, xA, yA, minvA, ccsA, ep, t0, writer);
        t0 += NSTEP;
        // odd half: serial block n+1, prologue block n+2
        prefetch_u(xA, yA, xp, yp, t0 + NSTEP, off);  // last loads block 124
        prologue(minvA, ccsA, xB, xA, SC, pl);
        serial(W2, P, Q, xlast, xB, yB, minvB, ccsB, ep, t0, writer);
        t0 += NSTEP;
    }
    // block 124 (t0 = 1984): prologue already in A
    serial(W2, P, Q, xlast, xA, yA, minvA, ccsA, ep, t0, writer);

    if (write_w) {
        float* wf = out + (size_t)NB * NT * NF;
#pragma unroll
        for (int i = 0; i < 8; i++) {
            int j = 16 * h + 2 * i;
            float w0, w1;
            unpack2(W2[i], w0, w1);
            if (valid) {
                wf[((size_t)b * NL + j) * NF + f] = w0;
                wf[((size_t)b * NL + j + 1) * NF + f] = w1;
            }
        }
    }
}

extern "C" void kernel_launch(void* const* d_in, const int* in_sizes, int n_in,
                              void* d_out, int out_size)
{
    const float* X  = (const float*)d_in[0];  // X_hat_mag [B,T,F]
    const float* Y  = (const float*)d_in[1];  // Y_mag     [B,T,F]
    const float* Wp = (const float*)d_in[2];  // W_prev    [B,L,F]
    float* out = (float*)d_out;

    long long need = (long long)NB * NT * NF + (long long)NB * NL * NF;
    int write_w = ((long long)out_size >= need) ? 1 : 0;

    // 32832 live threads (1026 warps) + 64 clamped duplicates; 257 blocks.
    nlms_kernel<<<257, 128>>>(X, Y, Wp, out, write_w);
}

// round 14
// speedup vs baseline: 1.0475x; 1.0475x over previous
#include <cuda_runtime.h>
#include <cuda_bf16.h>
#include <cstdint>

// DifferentiableNLMS: B=32, T=2000, F=513, L=32, mu=0.1, eps=1e-8
// ONE thread per (b,f) sequence - no lane split, no shuffles, no duplicated
// scalar work. 16-pair f32x2 ring (32 samples, mask 15) with phase-templated
// 16-step blocks; two-step lookahead (e1 corrected by lag-1 cross-corr CC);
// packed (S|CC) incremental prologue with EPS folded into the seed and all
// MUFU.RCPs hoisted off the serial chain. Launch 129x128 = 1 warp per SMSP
// on 129 SMs, uniform; warp loads are 32 consecutive f -> 128B coalesced.

#define NB 32
#define NT 2000
#define NF 513
#define NL 32
#define MU 0.1f
#define EPSV 1e-8f

#define NSEQ (NB * NF)         // 16416 sequences
#define NSTEP 16
#define NPB 8
#define NDBL 62                // 62*2+1 = 125 blocks of 16 steps

typedef unsigned long long u64;

__device__ __forceinline__ u64 ffma2(u64 a, u64 b, u64 c) {
    u64 d; asm("fma.rn.f32x2 %0, %1, %2, %3;" : "=l"(d) : "l"(a), "l"(b), "l"(c));
    return d;
}
__device__ __forceinline__ u64 fadd2(u64 a, u64 b) {
    u64 d; asm("add.rn.f32x2 %0, %1, %2;" : "=l"(d) : "l"(a), "l"(b));
    return d;
}
__device__ __forceinline__ u64 pack2(float lo, float hi) {
    u64 d; asm("mov.b64 %0, {%1, %2};" : "=l"(d) : "f"(lo), "f"(hi));
    return d;
}
__device__ __forceinline__ void unpack2(u64 v, float& lo, float& hi) {
    asm("mov.b64 {%0, %1}, %2;" : "=f"(lo), "=f"(hi) : "l"(v));
}
__device__ __forceinline__ float negf(float x) {   // sign flip on alu pipe
    return __int_as_float(__float_as_int(x) ^ 0x80000000);
}

__device__ __forceinline__ void prefetch(float (&x)[NSTEP], float (&y)[NSTEP],
                                         const float* __restrict__ xp,
                                         const float* __restrict__ yp, int t)
{
#pragma unroll
    for (int u = 0; u < NSTEP; u++) {
        x[u] = __ldg(xp + (size_t)(t + u) * NF);
        y[u] = __ldg(yp + (size_t)(t + u) * NF);
    }
}

// M0 = ring phase ((t0/2) mod 16): 0 or 8.
template <int M0>
__device__ __forceinline__ void run_block(
    u64 (&W2)[16], u64 (&P)[16], u64 (&Q)[16],
    u64& SC, float& xlast,
    const float (&xb)[NSTEP], const float (&yb)[NSTEP],
    float* __restrict__ ep, int t0, bool valid)
{
    float minv[NSTEP];
    float ccs[NPB];
    float xm1_0 = xlast;

    // ---- Prologue: packed (S | CC) incremental chain, X-only ----
    // lo(SC) = full-window norm + EPS (seeded); hi(SC) = lag-1 cross-corr.
    // Drops read OLD ring slots (32 samples back) before any insertion.
    {
        u64 sc = SC;
        float s0a[NPB], s1a[NPB], cca[NPB];
#pragma unroll
        for (int p = 0; p < NPB; p++) {
            const int m = (M0 + p) & 15;
            float a, b, bq, cq;
            unpack2(P[m], a, b);   // (x_{t-33}, x_{t-32})
            unpack2(Q[m], bq, cq); // (x_{t-32}, x_{t-31})
            float xm1 = p ? xb[2 * p - 1] : xm1_0;
            float x0 = xb[2 * p], x1 = xb[2 * p + 1];
            // S += x0^2 ; CC += xm1*x0
            sc = ffma2(pack2(x0, xm1), pack2(x0, x0), sc);
            // S -= b^2  ; CC -= a*b
            sc = ffma2(pack2(negf(b), negf(a)), pack2(b, b), sc);
            { float slo, shi; unpack2(sc, slo, shi); s0a[p] = slo; }
            // S += x1^2 ; CC += x0*x1
            sc = ffma2(pack2(x1, x0), pack2(x1, x1), sc);
            // S -= cq^2 ; CC -= bq*cq
            sc = ffma2(pack2(negf(cq), negf(bq)), pack2(cq, cq), sc);
            { float slo, shi; unpack2(sc, slo, shi); s1a[p] = slo; cca[p] = shi; }
        }
        SC = sc;
#pragma unroll
        for (int p = 0; p < NPB; p++) {
            minv[2 * p]     = __fdividef(MU, s0a[p]);  // EPS already inside S
            minv[2 * p + 1] = __fdividef(MU, s1a[p]);
            ccs[p] = cca[p];
        }
    }
    xlast = xb[NSTEP - 1];

    // ---- Serial recursion: 2 steps per iteration, no cross-lane traffic ----
#pragma unroll
    for (int p = 0; p < NPB; p++) {
        const int m = (M0 + p) & 15;
        float xm1 = p ? xb[2 * p - 1] : xm1_0;
        float x0 = xb[2 * p], x1 = xb[2 * p + 1];
        P[m] = pack2(xm1, x0);  // slot holds (x_{t-1}, x_t)
        Q[m] = pack2(x0, x1);   // slot holds (x_t, x_{t+1})

        // Full 32-tap dots, both phases, 8 accumulators.
        u64 a0 = 0, a1 = 0, a2 = 0, a3 = 0;
        u64 b0 = 0, b1 = 0, b2 = 0, b3 = 0;
#pragma unroll
        for (int i = 0; i < 16; i += 4) {
            a0 = ffma2(W2[i + 0], P[(m + 1 + i) & 15], a0);
            a1 = ffma2(W2[i + 1], P[(m + 2 + i) & 15], a1);
            a2 = ffma2(W2[i + 2], P[(m + 3 + i) & 15], a2);
            a3 = ffma2(W2[i + 3], P[(m + 4 + i) & 15], a3);
            b0 = ffma2(W2[i + 0], Q[(m + 1 + i) & 15], b0);
            b1 = ffma2(W2[i + 1], Q[(m + 2 + i) & 15], b1);
            b2 = ffma2(W2[i + 2], Q[(m + 3 + i) & 15], b2);
            b3 = ffma2(W2[i + 3], Q[(m + 4 + i) & 15], b3);
        }
        u64 ap = fadd2(fadd2(a0, a1), fadd2(a2, a3));
        u64 aq = fadd2(fadd2(b0, b1), fadd2(b2, b3));
        float plo, phi, qlo, qhi;
        unpack2(ap, plo, phi);
        unpack2(aq, qlo, qhi);
        float pt = plo + phi;
        float qt = qlo + qhi;

        float e0 = yb[2 * p] - pt;
        float c0 = e0 * minv[2 * p];
        float e1 = fmaf(-c0, ccs[p], yb[2 * p + 1] - qt);
        float c1 = e1 * minv[2 * p + 1];

        if (valid) {
            ep[(size_t)(t0 + 2 * p) * NF] = e0;
            ep[(size_t)(t0 + 2 * p + 1) * NF] = e1;
        }

        u64 c0p = pack2(c0, c0);
        u64 c1p = pack2(c1, c1);
#pragma unroll
        for (int i = 0; i < 16; i++) {
            W2[i] = ffma2(c1p, Q[(m + 1 + i) & 15],
                          ffma2(c0p, P[(m + 1 + i) & 15], W2[i]));
        }
    }
}

__global__ void __launch_bounds__(128, 1)
nlms_kernel(const float* __restrict__ X, const float* __restrict__ Y,
            const float* __restrict__ Wp, float* __restrict__ out,
            int write_w)
{
    int gtid = blockIdx.x * blockDim.x + threadIdx.x;
    bool valid = (gtid < NSEQ);
    int seq = valid ? gtid : (NSEQ - 1);   // clamp: no divergent exit
    int b = seq / NF;
    int f = seq - b * NF;

    size_t base = (size_t)b * NT * NF + f;
    const float* xp = X + base;
    const float* yp = Y + base;
    float* ep = out + base;                // E_hat_mag at offset 0

    u64 W2[16], P[16], Q[16];
#pragma unroll
    for (int i = 0; i < 16; i++) {
        float w0 = Wp[((size_t)b * NL + 2 * i) * NF + f];
        float w1 = Wp[((size_t)b * NL + 2 * i + 1) * NF + f];
        W2[i] = pack2(w0, w1);
        P[i] = 0;                          // zero pad: window starts empty
        Q[i] = 0;
    }
    // lo = norm (+EPS seeded), hi = lag-1 cross-correlation.
    u64 SC = pack2(EPSV, 0.f);
    float xlast = 0.f;

    float xA[NSTEP], yA[NSTEP], xB[NSTEP], yB[NSTEP];
    prefetch(xA, yA, xp, yp, 0);

    int t0 = 0;
#pragma unroll 1
    for (int dd = 0; dd < NDBL; dd++) {
        prefetch(xB, yB, xp, yp, t0 + NSTEP);
        run_block<0>(W2, P, Q, SC, xlast, xA, yA, ep, t0, valid);
        t0 += NSTEP;
        prefetch(xA, yA, xp, yp, t0 + NSTEP);  // last iter loads block 124
        run_block<8>(W2, P, Q, SC, xlast, xB, yB, ep, t0, valid);
        t0 += NSTEP;
    }
    run_block<0>(W2, P, Q, SC, xlast, xA, yA, ep, t0, valid);  // t0 = 1984

    if (write_w) {
        float* wf = out + (size_t)NB * NT * NF;  // W_final after E
#pragma unroll
        for (int i = 0; i < 16; i++) {
            float w0, w1;
            unpack2(W2[i], w0, w1);
            if (valid) {
                wf[((size_t)b * NL + 2 * i) * NF + f] = w0;
                wf[((size_t)b * NL + 2 * i + 1) * NF + f] = w1;
            }
        }
    }
}

extern "C" void kernel_launch(void* const* d_in, const int* in_sizes, int n_in,
                              void* d_out, int out_size)
{
    const float* X  = (const float*)d_in[0];  // X_hat_mag [B,T,F]
    const float* Y  = (const float*)d_in[1];  // Y_mag     [B,T,F]
    const float* Wp = (const float*)d_in[2];  // W_prev    [B,L,F]
    float* out = (float*)d_out;

    long long need = (long long)NB * NT * NF + (long long)NB * NL * NF;
    int write_w = ((long long)out_size >= need) ? 1 : 0;

    // 16416 sequences -> 129 blocks of 128 (96 clamped duplicates).
    // 1 block/SM, exactly 1 warp per SMSP; coalesced 128B warp loads.
    nlms_kernel<<<129, 128>>>(X, Y, Wp, out, write_w);
}